// round 2
// baseline (speedup 1.0000x reference)
#include <cuda_runtime.h>

// ConvLayer_6279242186805: submanifold sparse conv (K=27 offsets, P pairs each,
// Cin=Cout=32) + LeakyReLU(0.01) + BatchNorm1d training-stats normalize.
//
// Pipeline (all graph-capturable kernel launches, no allocs):
//   1) zero_kernel      : zero d_out (used as conv accumulator) + stats
//   2) conv_kernel      : gather -> [P,32]@W[k] -> scatter-add (red.v4.f32)
//   3) stats_kernel     : per-channel sum/sumsq of LeakyReLU(conv)
//   4) finalize_kernel  : mean/var -> per-channel scale/shift
//   5) norm_kernel      : in-place y = lrelu(x)*scale[c] + shift[c]

#define LRELU_SLOPE 0.01f
#define BN_EPS 1e-5f
#define CH 32            // Cin == Cout == 32

__device__ float g_sum[CH];
__device__ float g_sumsq[CH];
__device__ float g_scale[CH];
__device__ float g_shift[CH];

// ---------------------------------------------------------------------------
__global__ void zero_kernel(float4* __restrict__ out, int n4) {
    int i = blockIdx.x * blockDim.x + threadIdx.x;
    int stride = gridDim.x * blockDim.x;
    float4 z = make_float4(0.f, 0.f, 0.f, 0.f);
    for (; i < n4; i += stride) out[i] = z;
    if (blockIdx.x == 0 && threadIdx.x < CH) {
        g_sum[threadIdx.x] = 0.f;
        g_sumsq[threadIdx.x] = 0.f;
    }
}

// ---------------------------------------------------------------------------
// Conv: grid = (pair_chunks, K). Block = 128 threads = 4 warps.
// Each warp: weight column of W[k] in registers (lane = out channel),
// processes batches of 32 pairs: stage 32 gathered rows in smem (swizzled),
// then per pair broadcast-read via LDS.128 and FFMA into per-lane acc,
// finally pack to float4 on lanes 0..7 and red.global.add.v4.f32.

#define WARPS_PER_BLOCK 4
#define BATCH 32
#define BATCHES_PER_WARP 4
#define PAIRS_PER_BLOCK (WARPS_PER_BLOCK * BATCH * BATCHES_PER_WARP)  // 512

__global__ __launch_bounds__(128) void conv_kernel(
    const float* __restrict__ feat,
    const float* __restrict__ weight,
    const int*   __restrict__ pin,
    const int*   __restrict__ pout,
    float* __restrict__ out,
    int P)
{
    __shared__ float4 buf[WARPS_PER_BLOCK][BATCH * 8];  // 4KB per warp

    const int lane = threadIdx.x & 31;
    const int warp = threadIdx.x >> 5;
    const int k = blockIdx.y;

    // weight column for this lane: w[j] = W[k][j][lane]
    float w[CH];
    const float* wk = weight + (size_t)k * CH * CH;
#pragma unroll
    for (int j = 0; j < CH; j++) w[j] = wk[j * CH + lane];

    const int* pin_k  = pin  + (size_t)k * P;
    const int* pout_k = pout + (size_t)k * P;
    float4* bw = buf[warp];

    const int base = blockIdx.x * PAIRS_PER_BLOCK + warp * (BATCH * BATCHES_PER_WARP);

    for (int b = 0; b < BATCHES_PER_WARP; b++) {
        int p0 = base + b * BATCH;
        if (p0 >= P) break;
        int valid = P - p0;
        if (valid > BATCH) valid = BATCH;

        int pi = 0, po = 0;
        if (lane < valid) {
            pi = pin_k[p0 + lane];
            po = pout_k[p0 + lane];
        }

        // stage gathered row for pair 'lane' (swizzled by row to kill STS conflicts)
        const float4* frow = (const float4*)(feat + (size_t)pi * CH);
#pragma unroll
        for (int i = 0; i < 8; i++) {
            bw[lane * 8 + ((i + lane) & 7)] = frow[i];
        }
        __syncwarp();

#pragma unroll 4
        for (int q = 0; q < valid; q++) {
            float acc0 = 0.f, acc1 = 0.f;
#pragma unroll
            for (int i = 0; i < 8; i += 2) {
                float4 a = bw[q * 8 + ((i + q) & 7)];
                float4 c = bw[q * 8 + ((i + 1 + q) & 7)];
                acc0 = fmaf(a.x, w[4 * i + 0], acc0);
                acc0 = fmaf(a.y, w[4 * i + 1], acc0);
                acc0 = fmaf(a.z, w[4 * i + 2], acc0);
                acc0 = fmaf(a.w, w[4 * i + 3], acc0);
                acc1 = fmaf(c.x, w[4 * i + 4], acc1);
                acc1 = fmaf(c.y, w[4 * i + 5], acc1);
                acc1 = fmaf(c.z, w[4 * i + 6], acc1);
                acc1 = fmaf(c.w, w[4 * i + 7], acc1);
            }
            float acc = acc0 + acc1;

            int poq = __shfl_sync(0xffffffffu, po, q);
            // pack channel quads onto lanes 0..7
            int src = (lane & 7) * 4;
            float4 v;
            v.x = __shfl_sync(0xffffffffu, acc, src + 0);
            v.y = __shfl_sync(0xffffffffu, acc, src + 1);
            v.z = __shfl_sync(0xffffffffu, acc, src + 2);
            v.w = __shfl_sync(0xffffffffu, acc, src + 3);
            if (lane < 8) {
                float* dst = out + (size_t)poq * CH + lane * 4;
                asm volatile("red.global.add.v4.f32 [%0], {%1,%2,%3,%4};"
                             :: "l"(dst), "f"(v.x), "f"(v.y), "f"(v.z), "f"(v.w)
                             : "memory");
            }
        }
        __syncwarp();
    }
}

// ---------------------------------------------------------------------------
// Per-channel sum / sumsq of LeakyReLU(x). stride is a multiple of 32, so each
// thread's channel is fixed (= lane); block-reduce across warps, then 64
// atomics per block into g_sum/g_sumsq.
__global__ __launch_bounds__(256) void stats_kernel(const float* __restrict__ x, int n) {
    int tid = blockIdx.x * blockDim.x + threadIdx.x;
    int stride = gridDim.x * blockDim.x;
    float s = 0.f, s2 = 0.f;
    for (int i = tid; i < n; i += stride) {
        float v = x[i];
        v = (v >= 0.f) ? v : LRELU_SLOPE * v;
        s += v;
        s2 = fmaf(v, v, s2);
    }
    __shared__ float ss[8][CH];
    __shared__ float ss2[8][CH];
    int lane = threadIdx.x & 31, warp = threadIdx.x >> 5;
    ss[warp][lane] = s;
    ss2[warp][lane] = s2;
    __syncthreads();
    if (warp == 0) {
        float ts = 0.f, t2 = 0.f;
#pragma unroll
        for (int wi = 0; wi < 8; wi++) { ts += ss[wi][lane]; t2 += ss2[wi][lane]; }
        atomicAdd(&g_sum[lane], ts);
        atomicAdd(&g_sumsq[lane], t2);
    }
}

// ---------------------------------------------------------------------------
__global__ void finalize_kernel(const float* __restrict__ gamma,
                                const float* __restrict__ beta,
                                float inv_n) {
    int l = threadIdx.x;
    float mean = g_sum[l] * inv_n;
    float var  = g_sumsq[l] * inv_n - mean * mean;
    float a = gamma[l] * rsqrtf(var + BN_EPS);
    g_scale[l] = a;
    g_shift[l] = fmaf(-mean, a, beta[l]);
}

// ---------------------------------------------------------------------------
__global__ __launch_bounds__(256) void norm_kernel(float4* __restrict__ out, int n4) {
    __shared__ float sc[CH], sh[CH];
    if (threadIdx.x < CH) { sc[threadIdx.x] = g_scale[threadIdx.x]; sh[threadIdx.x] = g_shift[threadIdx.x]; }
    __syncthreads();
    int i = blockIdx.x * blockDim.x + threadIdx.x;
    int stride = gridDim.x * blockDim.x;
    for (; i < n4; i += stride) {
        float4 v = out[i];
        int c = (i & 7) * 4;  // channel of first component (row = 32 floats)
        float x;
        x = (v.x >= 0.f) ? v.x : LRELU_SLOPE * v.x;  v.x = fmaf(x, sc[c + 0], sh[c + 0]);
        x = (v.y >= 0.f) ? v.y : LRELU_SLOPE * v.y;  v.y = fmaf(x, sc[c + 1], sh[c + 1]);
        x = (v.z >= 0.f) ? v.z : LRELU_SLOPE * v.z;  v.z = fmaf(x, sc[c + 2], sh[c + 2]);
        x = (v.w >= 0.f) ? v.w : LRELU_SLOPE * v.w;  v.w = fmaf(x, sc[c + 3], sh[c + 3]);
        out[i] = v;
    }
}

// ---------------------------------------------------------------------------
extern "C" void kernel_launch(void* const* d_in, const int* in_sizes, int n_in,
                              void* d_out, int out_size) {
    const float* feat   = (const float*)d_in[0];   // [N, 32]
    const float* weight = (const float*)d_in[1];   // [K, 32, 32]
    const float* gamma  = (const float*)d_in[2];   // [32]
    const float* beta   = (const float*)d_in[3];   // [32]
    const int*   pin    = (const int*)d_in[4];     // [K, P]
    const int*   pout   = (const int*)d_in[5];     // [K, P]
    float* out = (float*)d_out;

    const int N  = in_sizes[0] / CH;
    const int K  = in_sizes[1] / (CH * CH);
    const int P  = in_sizes[4] / K;
    const int n  = N * CH;
    const int n4 = n / 4;

    // 1) zero accumulator + stats
    zero_kernel<<<2048, 256>>>((float4*)out, n4);

    // 2) conv scatter-add
    dim3 grid((P + PAIRS_PER_BLOCK - 1) / PAIRS_PER_BLOCK, K);
    conv_kernel<<<grid, 128>>>(feat, weight, pin, pout, out, P);

    // 3) BN stats
    stats_kernel<<<1184, 256>>>(out, n);

    // 4) scale/shift
    finalize_kernel<<<1, 32>>>(gamma, beta, 1.0f / (float)N);

    // 5) normalize in place
    norm_kernel<<<2048, 256>>>((float4*)out, n4);
}

// round 3
// speedup vs baseline: 1.0082x; 1.0082x over previous
#include <cuda_runtime.h>

// ConvLayer_6279242186805: submanifold sparse conv (K=27 offsets, P pairs each,
// Cin=Cout=32) + LeakyReLU(0.01) + BatchNorm1d training-stats normalize.
//
// R2: inner product uses packed fma.rn.f32x2 (FFMA2) — 2 fp32 MACs/instr.
// LDS.128 naturally yields aligned 64-bit register pairs, so the packed
// operands are free; weight column packed into 16 b64 regs at kernel start.

#define LRELU_SLOPE 0.01f
#define BN_EPS 1e-5f
#define CH 32            // Cin == Cout == 32

__device__ float g_sum[CH];
__device__ float g_sumsq[CH];
__device__ float g_scale[CH];
__device__ float g_shift[CH];

// ---------------------------------------------------------------------------
__global__ void zero_kernel(float4* __restrict__ out, int n4) {
    int i = blockIdx.x * blockDim.x + threadIdx.x;
    int stride = gridDim.x * blockDim.x;
    float4 z = make_float4(0.f, 0.f, 0.f, 0.f);
    for (; i < n4; i += stride) out[i] = z;
    if (blockIdx.x == 0 && threadIdx.x < CH) {
        g_sum[threadIdx.x] = 0.f;
        g_sumsq[threadIdx.x] = 0.f;
    }
}

// ---------------------------------------------------------------------------
// Conv: grid = (pair_chunks, K). Block = 128 threads = 4 warps.
// Warp: weight column of W[k] packed as 16 f32x2 regs (lane = out channel),
// batches of 32 pairs: stage gathered rows in smem (swizzled), per pair
// broadcast-read via LDS.128 (as ulonglong2 -> two f32x2 operands), 16 FFMA2,
// then pack channel quads onto lanes 0..7 and red.global.add.v4.f32.

#define WARPS_PER_BLOCK 4
#define BATCH 32
#define BATCHES_PER_WARP 4
#define PAIRS_PER_BLOCK (WARPS_PER_BLOCK * BATCH * BATCHES_PER_WARP)  // 512

__global__ __launch_bounds__(128) void conv_kernel(
    const float* __restrict__ feat,
    const float* __restrict__ weight,
    const int*   __restrict__ pin,
    const int*   __restrict__ pout,
    float* __restrict__ out,
    int P)
{
    __shared__ ulonglong2 buf[WARPS_PER_BLOCK][BATCH * 8];  // 4KB per warp

    const int lane = threadIdx.x & 31;
    const int warp = threadIdx.x >> 5;
    const int k = blockIdx.y;

    // weight column for this lane, packed into 16 f32x2 (b64) registers:
    // w2[j] = { W[k][2j][lane], W[k][2j+1][lane] }
    const float* wk = weight + (size_t)k * CH * CH;
    unsigned long long w2[CH / 2];
#pragma unroll
    for (int j = 0; j < CH / 2; j++) {
        float lo = wk[(2 * j) * CH + lane];
        float hi = wk[(2 * j + 1) * CH + lane];
        asm("mov.b64 %0, {%1, %2};" : "=l"(w2[j]) : "f"(lo), "f"(hi));
    }

    const int* pin_k  = pin  + (size_t)k * P;
    const int* pout_k = pout + (size_t)k * P;
    ulonglong2* bw = buf[warp];

    const int base = blockIdx.x * PAIRS_PER_BLOCK + warp * (BATCH * BATCHES_PER_WARP);

    for (int b = 0; b < BATCHES_PER_WARP; b++) {
        int p0 = base + b * BATCH;
        if (p0 >= P) break;
        int valid = P - p0;
        if (valid > BATCH) valid = BATCH;

        int pi = 0, po = 0;
        if (lane < valid) {
            pi = pin_k[p0 + lane];
            po = pout_k[p0 + lane];
        }

        // stage gathered row for pair 'lane' (swizzled by row to kill STS conflicts)
        const ulonglong2* frow = (const ulonglong2*)(feat + (size_t)pi * CH);
#pragma unroll
        for (int i = 0; i < 8; i++) {
            bw[lane * 8 + ((i + lane) & 7)] = frow[i];
        }
        __syncwarp();

#pragma unroll 4
        for (int q = 0; q < valid; q++) {
            // two independent packed accumulators for ILP
            unsigned long long acc0 = 0ull, acc1 = 0ull;  // {0.f, 0.f} bit pattern
#pragma unroll
            for (int i = 0; i < 8; i += 2) {
                ulonglong2 a = bw[q * 8 + ((i + q) & 7)];       // floats 4i   .. 4i+3
                ulonglong2 c = bw[q * 8 + ((i + 1 + q) & 7)];   // floats 4i+4 .. 4i+7
                asm("fma.rn.f32x2 %0, %1, %2, %0;" : "+l"(acc0) : "l"(a.x), "l"(w2[2 * i + 0]));
                asm("fma.rn.f32x2 %0, %1, %2, %0;" : "+l"(acc1) : "l"(a.y), "l"(w2[2 * i + 1]));
                asm("fma.rn.f32x2 %0, %1, %2, %0;" : "+l"(acc0) : "l"(c.x), "l"(w2[2 * i + 2]));
                asm("fma.rn.f32x2 %0, %1, %2, %0;" : "+l"(acc1) : "l"(c.y), "l"(w2[2 * i + 3]));
            }
            float a0lo, a0hi, a1lo, a1hi;
            asm("mov.b64 {%0, %1}, %2;" : "=f"(a0lo), "=f"(a0hi) : "l"(acc0));
            asm("mov.b64 {%0, %1}, %2;" : "=f"(a1lo), "=f"(a1hi) : "l"(acc1));
            float acc = (a0lo + a1lo) + (a0hi + a1hi);

            int poq = __shfl_sync(0xffffffffu, po, q);
            // pack channel quads onto lanes 0..7
            int src = (lane & 7) * 4;
            float4 v;
            v.x = __shfl_sync(0xffffffffu, acc, src + 0);
            v.y = __shfl_sync(0xffffffffu, acc, src + 1);
            v.z = __shfl_sync(0xffffffffu, acc, src + 2);
            v.w = __shfl_sync(0xffffffffu, acc, src + 3);
            if (lane < 8) {
                float* dst = out + (size_t)poq * CH + lane * 4;
                asm volatile("red.global.add.v4.f32 [%0], {%1,%2,%3,%4};"
                             :: "l"(dst), "f"(v.x), "f"(v.y), "f"(v.z), "f"(v.w)
                             : "memory");
            }
        }
        __syncwarp();
    }
}

// ---------------------------------------------------------------------------
// Per-channel sum / sumsq of LeakyReLU(x). stride is a multiple of 32, so each
// thread's channel is fixed (= lane); block-reduce across warps, then 64
// atomics per block into g_sum/g_sumsq.
__global__ __launch_bounds__(256) void stats_kernel(const float* __restrict__ x, int n) {
    int tid = blockIdx.x * blockDim.x + threadIdx.x;
    int stride = gridDim.x * blockDim.x;
    float s = 0.f, s2 = 0.f;
    for (int i = tid; i < n; i += stride) {
        float v = x[i];
        v = (v >= 0.f) ? v : LRELU_SLOPE * v;
        s += v;
        s2 = fmaf(v, v, s2);
    }
    __shared__ float ss[8][CH];
    __shared__ float ss2[8][CH];
    int lane = threadIdx.x & 31, warp = threadIdx.x >> 5;
    ss[warp][lane] = s;
    ss2[warp][lane] = s2;
    __syncthreads();
    if (warp == 0) {
        float ts = 0.f, t2 = 0.f;
#pragma unroll
        for (int wi = 0; wi < 8; wi++) { ts += ss[wi][lane]; t2 += ss2[wi][lane]; }
        atomicAdd(&g_sum[lane], ts);
        atomicAdd(&g_sumsq[lane], t2);
    }
}

// ---------------------------------------------------------------------------
__global__ void finalize_kernel(const float* __restrict__ gamma,
                                const float* __restrict__ beta,
                                float inv_n) {
    int l = threadIdx.x;
    float mean = g_sum[l] * inv_n;
    float var  = g_sumsq[l] * inv_n - mean * mean;
    float a = gamma[l] * rsqrtf(var + BN_EPS);
    g_scale[l] = a;
    g_shift[l] = fmaf(-mean, a, beta[l]);
}

// ---------------------------------------------------------------------------
__global__ __launch_bounds__(256) void norm_kernel(float4* __restrict__ out, int n4) {
    __shared__ float sc[CH], sh[CH];
    if (threadIdx.x < CH) { sc[threadIdx.x] = g_scale[threadIdx.x]; sh[threadIdx.x] = g_shift[threadIdx.x]; }
    __syncthreads();
    int i = blockIdx.x * blockDim.x + threadIdx.x;
    int stride = gridDim.x * blockDim.x;
    for (; i < n4; i += stride) {
        float4 v = out[i];
        int c = (i & 7) * 4;  // channel of first component (row = 32 floats)
        float x;
        x = (v.x >= 0.f) ? v.x : LRELU_SLOPE * v.x;  v.x = fmaf(x, sc[c + 0], sh[c + 0]);
        x = (v.y >= 0.f) ? v.y : LRELU_SLOPE * v.y;  v.y = fmaf(x, sc[c + 1], sh[c + 1]);
        x = (v.z >= 0.f) ? v.z : LRELU_SLOPE * v.z;  v.z = fmaf(x, sc[c + 2], sh[c + 2]);
        x = (v.w >= 0.f) ? v.w : LRELU_SLOPE * v.w;  v.w = fmaf(x, sc[c + 3], sh[c + 3]);
        out[i] = v;
    }
}

// ---------------------------------------------------------------------------
extern "C" void kernel_launch(void* const* d_in, const int* in_sizes, int n_in,
                              void* d_out, int out_size) {
    const float* feat   = (const float*)d_in[0];   // [N, 32]
    const float* weight = (const float*)d_in[1];   // [K, 32, 32]
    const float* gamma  = (const float*)d_in[2];   // [32]
    const float* beta   = (const float*)d_in[3];   // [32]
    const int*   pin    = (const int*)d_in[4];     // [K, P]
    const int*   pout   = (const int*)d_in[5];     // [K, P]
    float* out = (float*)d_out;

    const int N  = in_sizes[0] / CH;
    const int K  = in_sizes[1] / (CH * CH);
    const int P  = in_sizes[4] / K;
    const int n  = N * CH;
    const int n4 = n / 4;

    // 1) zero accumulator + stats
    zero_kernel<<<2048, 256>>>((float4*)out, n4);

    // 2) conv scatter-add
    dim3 grid((P + PAIRS_PER_BLOCK - 1) / PAIRS_PER_BLOCK, K);
    conv_kernel<<<grid, 128>>>(feat, weight, pin, pout, out, P);

    // 3) BN stats
    stats_kernel<<<1184, 256>>>(out, n);

    // 4) scale/shift
    finalize_kernel<<<1, 32>>>(gamma, beta, 1.0f / (float)N);

    // 5) normalize in place
    norm_kernel<<<2048, 256>>>((float4*)out, n4);
}